// round 8
// baseline (speedup 1.0000x reference)
#include <cuda_runtime.h>
#include <math.h>

// d(x,y) = a*dy^2 + b*dx^2 + c*dy*dx  (dy=y-ly, dx=x-lx); m = max(1-d, 0)
// expanded: d = a y^2 + b x^2 + c x y + D y + E x + F
// record: A=(nb,nc,nE,na)  B=(nD,F1,wr,wg)  wb   with nb=-b etc., F1=1-F
// render per (row,pt): ng = nc*y + nE ; h1 = (na*y + nD)*y + F1
// tile cull (sqrt/div-free, conservative): det = ab - c^2/4
//   max(|ly-yc|-hy,0)^2 * det <= b  AND  max(|lx-xc|-hx,0)^2 * det <= a

#define TW  64        // tile width  (pixels)
#define TH  32        // tile height (rows)
#define TPB 1024      // 32 warps; warp w renders tile row w; 2 px/thread

__global__ __launch_bounds__(TPB)
void fused_kernel(const float* __restrict__ loc,
                  const float* __restrict__ moff,
                  const float* __restrict__ msfo,
                  const float* __restrict__ colors,
                  const float* __restrict__ alphas,
                  float* __restrict__ out,
                  int H, int W, int P, float ratio)
{
    extern __shared__ float smem[];
    float4* s_A  = (float4*)smem;              // P float4
    float4* s_B  = s_A + P;                    // P float4
    float*  s_wb = (float*)(s_B + P);          // P floats
    __shared__ int s_cnt;

    const int tid  = threadIdx.x;
    const int lane = tid & 31;
    if (tid == 0) s_cnt = 0;
    __syncthreads();

    // ---- Tile geometry ----
    const float dyp = 2.0f / (float)(H - 1);
    const float dxp = 2.0f * ratio / (float)(W - 1);
    const int tx = blockIdx.x, ty = blockIdx.y;

    const float hy = 0.5f * (float)(TH - 1) * dyp;
    const float hx = 0.5f * (float)(TW - 1) * dxp;
    const float yc = -1.0f  + (float)(ty * TH) * dyp + hy;
    const float xc = -ratio + (float)(tx * TW) * dxp + hx;

    const float sP = 0.5f * sqrtf((float)P);

    // ---- Phase 1: prep + tile cull + compaction (direct global reads) ----
    for (int p0 = 0; p0 < P; p0 += TPB) {
        const int p = p0 + tid;
        bool act = false;
        float a = 0.f, b = 0.f, c = 0.f, ly = 0.f, lx = 0.f;
        if (p < P) {
            float  ms = __ldg(msfo + p);
            float4 m4 = __ldg((const float4*)moff + p);
            float2 l2 = __ldg((const float2*)loc + p);

            float scale = sP * __expf(ms);
            float T00 = m4.x + scale, T01 = m4.y;
            float T10 = m4.z,         T11 = m4.w + scale;

            a = T00 * T00 + T01 * T01;
            b = T10 * T10 + T11 * T11;
            c = 2.0f * (T00 * T10 + T01 * T11);
            ly = l2.x; lx = l2.y;

            float det = fmaf(a, b, -0.25f * c * c);
            float tdy = fmaxf(fabsf(ly - yc) - hy, 0.0f);
            float tdx = fmaxf(fabsf(lx - xc) - hx, 0.0f);
            act = (tdy * tdy * det <= b) && (tdx * tdx * det <= a);
        }
        unsigned msk = __ballot_sync(0xffffffffu, act);
        if (msk) {
            int leader = __ffs(msk) - 1;
            int base = 0;
            if (lane == leader) base = atomicAdd(&s_cnt, __popc(msk));
            base = __shfl_sync(0xffffffffu, base, leader);
            int pos = base + __popc(msk & ((1u << lane) - 1u));
            if (act) {
                float D = -(2.0f * a * ly + c * lx);
                float E = -(2.0f * b * lx + c * ly);
                float F = a * ly * ly + b * lx * lx + c * lx * ly;
                float al = __ldg(alphas + p);
                float wr = __ldg(colors + 3 * p + 0) * al;
                float wg = __ldg(colors + 3 * p + 1) * al;
                float wb = __ldg(colors + 3 * p + 2) * al;
                s_A[pos]  = make_float4(-b, -c, -E, -a);
                s_B[pos]  = make_float4(-D, 1.0f - F, wr, wg);
                s_wb[pos] = wb;
            }
        }
    }
    __syncthreads();
    const int count = s_cnt;

    // ---- Phase 2: render 2 adjacent px/thread; warp w == tile row w ----
    const int rowi = tid >> 5;                 // 0..TH-1 (uniform per warp)
    const int gy = ty * TH + rowi;
    const int gx = tx * TW + lane * 2;
    const float y  = -1.0f  + (float)gy * dyp;
    const float xa = -ratio + (float)gx * dxp;
    const float xb = xa + dxp;

    float ar0 = 0.f, ag0 = 0.f, ab0 = 0.f;
    float ar1 = 0.f, ag1 = 0.f, ab1 = 0.f;

    for (int p = 0; p < count; p++) {
        const float4 rA = s_A[p];
        const float4 rB = s_B[p];
        const float  wb = s_wb[p];

        float ng = fmaf(y, rA.y, rA.z);                      // nc*y + nE
        float h1 = fmaf(y, fmaf(y, rA.w, rB.x), rB.y);       // (na*y+nD)*y + F1

        float w0 = fmaf(xa, fmaf(xa, rA.x, ng), h1);
        float w1 = fmaf(xb, fmaf(xb, rA.x, ng), h1);
        float m0 = fmaxf(w0, 0.0f);
        float m1 = fmaxf(w1, 0.0f);

        ar0 = fmaf(m0, rB.z, ar0);  ar1 = fmaf(m1, rB.z, ar1);
        ag0 = fmaf(m0, rB.w, ag0);  ag1 = fmaf(m1, rB.w, ag1);
        ab0 = fmaf(m0, wb,  ab0);   ab1 = fmaf(m1, wb,  ab1);
    }

    // ---- sigmoid(4*canvas) epilogue + store (2 px = 6 contiguous floats) ----
    if (gy < H && gx + 1 < W) {
        float* o = out + ((size_t)gy * W + gx) * 3;
        o[0] = 1.0f / (1.0f + __expf(-4.0f * ar0));
        o[1] = 1.0f / (1.0f + __expf(-4.0f * ag0));
        o[2] = 1.0f / (1.0f + __expf(-4.0f * ab0));
        o[3] = 1.0f / (1.0f + __expf(-4.0f * ar1));
        o[4] = 1.0f / (1.0f + __expf(-4.0f * ag1));
        o[5] = 1.0f / (1.0f + __expf(-4.0f * ab1));
    }
}

extern "C" void kernel_launch(void* const* d_in, const int* in_sizes, int n_in,
                              void* d_out, int out_size)
{
    const float* loc    = (const float*)d_in[2];
    const float* moff   = (const float*)d_in[3];
    const float* msfo   = (const float*)d_in[4];
    const float* colors = (const float*)d_in[5];
    const float* alphas = (const float*)d_in[6];
    float* out = (float*)d_out;

    int P = in_sizes[2] / 2;             // locations has P*2 elements
    int HW = out_size / 3;               // output is H*W*3
    int H = (int)(sqrt((double)HW) + 0.5);
    int W = HW / H;
    float ratio = (float)W / (float)H;

    size_t smem = (size_t)P * (2 * sizeof(float4) + sizeof(float)); // 18 KB @P=512
    cudaFuncSetAttribute(fused_kernel,
                         cudaFuncAttributeMaxDynamicSharedMemorySize, (int)smem);

    dim3 grid((W + TW - 1) / TW, (H + TH - 1) / TH);
    fused_kernel<<<grid, TPB, smem>>>(loc, moff, msfo, colors, alphas,
                                      out, H, W, P, ratio);
}

// round 9
// speedup vs baseline: 1.2407x; 1.2407x over previous
#include <cuda_runtime.h>
#include <math.h>

// d(x,y) = a*dy^2 + b*dx^2 + c*dy*dx  (dy=y-ly, dx=x-lx); m = max(1-d, 0)
// expanded: d = a y^2 + b x^2 + c x y + D y + E x + F
// record: A=(nb,nc,nE,na)  B=(nD,F1,wr,wg)  wb   with nb=-b etc., F1=1-F
// render per (row,pt): ng = nc*y + nE ; h1 = (na*y + nD)*y + F1
// tile cull (sqrt/div-free, conservative): det = ab - c^2/4
//   max(|ly-yc|-hy,0)^2 * det <= b  AND  max(|lx-xc|-hx,0)^2 * det <= a

#define TW  64        // tile width  (pixels)
#define TH  16        // tile height (rows)
#define TPB 256       // 16 threads per row, 4 consecutive px per thread

__device__ __forceinline__ float sigm4(float v) {
    return 1.0f / (1.0f + __expf(-4.0f * v));
}

__global__ __launch_bounds__(TPB)
void fused_kernel(const float* __restrict__ loc,
                  const float* __restrict__ moff,
                  const float* __restrict__ msfo,
                  const float* __restrict__ colors,
                  const float* __restrict__ alphas,
                  float* __restrict__ out,
                  int H, int W, int P, float ratio)
{
    extern __shared__ float smem[];
    float4* s_A  = (float4*)smem;              // P float4
    float4* s_B  = s_A + P;                    // P float4
    float*  s_wb = (float*)(s_B + P);          // P floats
    __shared__ int s_cnt;

    const int tid  = threadIdx.x;
    const int lane = tid & 31;
    if (tid == 0) s_cnt = 0;
    __syncthreads();

    // ---- Tile geometry ----
    const float dyp = 2.0f / (float)(H - 1);
    const float dxp = 2.0f * ratio / (float)(W - 1);
    const int tx = blockIdx.x, ty = blockIdx.y;

    const float hy = 0.5f * (float)(TH - 1) * dyp;
    const float hx = 0.5f * (float)(TW - 1) * dxp;
    const float yc = -1.0f  + (float)(ty * TH) * dyp + hy;
    const float xc = -ratio + (float)(tx * TW) * dxp + hx;

    const float sP = 0.5f * sqrtf((float)P);

    // ---- Phase 1: prep + tile cull + compaction (direct global reads) ----
    for (int p0 = 0; p0 < P; p0 += TPB) {
        const int p = p0 + tid;
        bool act = false;
        float a = 0.f, b = 0.f, c = 0.f, ly = 0.f, lx = 0.f;
        if (p < P) {
            float  ms = __ldg(msfo + p);
            float4 m4 = __ldg((const float4*)moff + p);
            float2 l2 = __ldg((const float2*)loc + p);

            float scale = sP * __expf(ms);
            float T00 = m4.x + scale, T01 = m4.y;
            float T10 = m4.z,         T11 = m4.w + scale;

            a = T00 * T00 + T01 * T01;
            b = T10 * T10 + T11 * T11;
            c = 2.0f * (T00 * T10 + T01 * T11);
            ly = l2.x; lx = l2.y;

            float det = fmaf(a, b, -0.25f * c * c);
            float tdy = fmaxf(fabsf(ly - yc) - hy, 0.0f);
            float tdx = fmaxf(fabsf(lx - xc) - hx, 0.0f);
            act = (tdy * tdy * det <= b) && (tdx * tdx * det <= a);
        }
        unsigned msk = __ballot_sync(0xffffffffu, act);
        if (msk) {
            int leader = __ffs(msk) - 1;
            int base = 0;
            if (lane == leader) base = atomicAdd(&s_cnt, __popc(msk));
            base = __shfl_sync(0xffffffffu, base, leader);
            int pos = base + __popc(msk & ((1u << lane) - 1u));
            if (act) {
                float D = -(2.0f * a * ly + c * lx);
                float E = -(2.0f * b * lx + c * ly);
                float F = a * ly * ly + b * lx * lx + c * lx * ly;
                float al = __ldg(alphas + p);
                float wr = __ldg(colors + 3 * p + 0) * al;
                float wg = __ldg(colors + 3 * p + 1) * al;
                float wb = __ldg(colors + 3 * p + 2) * al;
                s_A[pos]  = make_float4(-b, -c, -E, -a);
                s_B[pos]  = make_float4(-D, 1.0f - F, wr, wg);
                s_wb[pos] = wb;
            }
        }
    }
    __syncthreads();
    const int count = s_cnt;

    // ---- Phase 2: render 4 consecutive px/thread; 16 threads per row ----
    const int rowi = tid >> 4;                 // 0..TH-1
    const int coli = (tid & 15) * 4;           // 0,4,...,60
    const int gy = ty * TH + rowi;
    const int gx = tx * TW + coli;
    const float y  = -1.0f  + (float)gy * dyp;
    const float x0 = -ratio + (float)gx * dxp;
    const float x1 = x0 + dxp;
    const float x2 = x1 + dxp;
    const float x3 = x2 + dxp;

    float ar0 = 0.f, ag0 = 0.f, ab0 = 0.f;
    float ar1 = 0.f, ag1 = 0.f, ab1 = 0.f;
    float ar2 = 0.f, ag2 = 0.f, ab2 = 0.f;
    float ar3 = 0.f, ag3 = 0.f, ab3 = 0.f;

#pragma unroll 2
    for (int p = 0; p < count; p++) {
        const float4 rA = s_A[p];
        const float4 rB = s_B[p];
        const float  wb = s_wb[p];

        float ng = fmaf(y, rA.y, rA.z);                      // nc*y + nE
        float h1 = fmaf(y, fmaf(y, rA.w, rB.x), rB.y);       // (na*y+nD)*y + F1

        float m0 = fmaxf(fmaf(x0, fmaf(x0, rA.x, ng), h1), 0.0f);
        float m1 = fmaxf(fmaf(x1, fmaf(x1, rA.x, ng), h1), 0.0f);
        float m2 = fmaxf(fmaf(x2, fmaf(x2, rA.x, ng), h1), 0.0f);
        float m3 = fmaxf(fmaf(x3, fmaf(x3, rA.x, ng), h1), 0.0f);

        ar0 = fmaf(m0, rB.z, ar0);  ar1 = fmaf(m1, rB.z, ar1);
        ar2 = fmaf(m2, rB.z, ar2);  ar3 = fmaf(m3, rB.z, ar3);
        ag0 = fmaf(m0, rB.w, ag0);  ag1 = fmaf(m1, rB.w, ag1);
        ag2 = fmaf(m2, rB.w, ag2);  ag3 = fmaf(m3, rB.w, ag3);
        ab0 = fmaf(m0, wb,  ab0);   ab1 = fmaf(m1, wb,  ab1);
        ab2 = fmaf(m2, wb,  ab2);   ab3 = fmaf(m3, wb,  ab3);
    }

    // ---- sigmoid(4*canvas) epilogue; 12 floats = 3x STG.128 ----
    if (gy < H && gx + 3 < W) {
        float4 o0 = make_float4(sigm4(ar0), sigm4(ag0), sigm4(ab0), sigm4(ar1));
        float4 o1 = make_float4(sigm4(ag1), sigm4(ab1), sigm4(ar2), sigm4(ag2));
        float4 o2 = make_float4(sigm4(ab2), sigm4(ar3), sigm4(ag3), sigm4(ab3));
        float4* o = (float4*)(out + ((size_t)gy * W + gx) * 3);
        o[0] = o0;
        o[1] = o1;
        o[2] = o2;
    }
}

extern "C" void kernel_launch(void* const* d_in, const int* in_sizes, int n_in,
                              void* d_out, int out_size)
{
    const float* loc    = (const float*)d_in[2];
    const float* moff   = (const float*)d_in[3];
    const float* msfo   = (const float*)d_in[4];
    const float* colors = (const float*)d_in[5];
    const float* alphas = (const float*)d_in[6];
    float* out = (float*)d_out;

    int P = in_sizes[2] / 2;             // locations has P*2 elements
    int HW = out_size / 3;               // output is H*W*3
    int H = (int)(sqrt((double)HW) + 0.5);
    int W = HW / H;
    float ratio = (float)W / (float)H;

    size_t smem = (size_t)P * (2 * sizeof(float4) + sizeof(float)); // 18 KB @P=512
    cudaFuncSetAttribute(fused_kernel,
                         cudaFuncAttributeMaxDynamicSharedMemorySize, (int)smem);

    dim3 grid((W + TW - 1) / TW, (H + TH - 1) / TH);
    fused_kernel<<<grid, TPB, smem>>>(loc, moff, msfo, colors, alphas,
                                      out, H, W, P, ratio);
}